// round 1
// baseline (speedup 1.0000x reference)
#include <cuda_runtime.h>
#include <math.h>

#define N_NODES 4096
#define KDIM    512      // all three GEMMs are [4096x512]@[512x64]
#define D_H     64
#define HEADS   8
#define MAXD    192      // degree cap: Binom(4096,1/128) mean 32, 192 is ~28 sigma
#define CH      32       // neighbor chunk staged in smem

// ---------------- scratch (no allocations allowed) ----------------
__device__ float g_x [N_NODES * D_H];            // per-layer projected features
__device__ float g_el[N_NODES * HEADS];
__device__ float g_er[N_NODES * HEADS];
__device__ float g_h1[N_NODES * D_H * HEADS];    // layer-0 output (4096x512)
__device__ float g_h2[N_NODES * D_H * HEADS];    // layer-1 output (4096x512)
__device__ int   g_cols[N_NODES * MAXD];
__device__ int   g_deg [N_NODES];

// ---------------- CSR build: warp per row, ordered ballot compaction ------
__global__ __launch_bounds__(256) void build_csr_kernel(const float* __restrict__ adj) {
    int warp = (blockIdx.x * blockDim.x + threadIdx.x) >> 5;
    int lane = threadIdx.x & 31;
    if (warp >= N_NODES) return;
    const float4* a = reinterpret_cast<const float4*>(adj + (size_t)warp * N_NODES);
    int* out = g_cols + warp * MAXD;
    int base = 0;
    for (int j0 = 0; j0 < N_NODES; j0 += 128) {
        float4 v = a[(j0 >> 2) + lane];
        float vv[4] = {v.x, v.y, v.z, v.w};
        #pragma unroll
        for (int c = 0; c < 4; c++) {
            unsigned m = __ballot_sync(0xffffffffu, vv[c] != 0.0f);
            if (vv[c] != 0.0f) {
                int pos = base + __popc(m & ((1u << lane) - 1u));
                if (pos < MAXD) out[pos] = j0 + lane * 4 + c;
            }
            base += __popc(m);
        }
    }
    if (lane == 0) g_deg[warp] = base < MAXD ? base : MAXD;
}

// ---------------- GEMM: C[4096x64] = A[4096x512] @ B[512x64], fp32 --------
// BM=32, BN=64, BK=32, 256 threads (16x16), 2x4 micro-tile. 128 blocks.
__global__ __launch_bounds__(256) void gemm_kernel(const float* __restrict__ A,
                                                   const float* __restrict__ B,
                                                   float* __restrict__ C) {
    __shared__ float As[32][33];
    __shared__ float Bs[32][64];
    int tid = threadIdx.x;
    int tx = tid & 15, ty = tid >> 4;
    int rowBase = blockIdx.x * 32;
    float acc[2][4] = {{0.f,0.f,0.f,0.f},{0.f,0.f,0.f,0.f}};

    for (int kt = 0; kt < KDIM; kt += 32) {
        {   // A tile: 32 rows x 32 k, one float4 per thread
            int r  = tid >> 3;
            int k4 = (tid & 7) << 2;
            float4 v = *reinterpret_cast<const float4*>(A + (size_t)(rowBase + r) * KDIM + kt + k4);
            As[r][k4+0] = v.x; As[r][k4+1] = v.y; As[r][k4+2] = v.z; As[r][k4+3] = v.w;
        }
        {   // B tile: 32 k x 64 cols, two float4 per thread
            int r  = tid >> 4;
            int c4 = (tid & 15) << 2;
            *reinterpret_cast<float4*>(&Bs[r][c4])      = *reinterpret_cast<const float4*>(B + (size_t)(kt + r)      * 64 + c4);
            *reinterpret_cast<float4*>(&Bs[r + 16][c4]) = *reinterpret_cast<const float4*>(B + (size_t)(kt + r + 16) * 64 + c4);
        }
        __syncthreads();
        #pragma unroll
        for (int k = 0; k < 32; k++) {
            float a0 = As[ty*2][k], a1 = As[ty*2+1][k];
            float4 b = *reinterpret_cast<const float4*>(&Bs[k][tx*4]);
            acc[0][0] += a0*b.x; acc[0][1] += a0*b.y; acc[0][2] += a0*b.z; acc[0][3] += a0*b.w;
            acc[1][0] += a1*b.x; acc[1][1] += a1*b.y; acc[1][2] += a1*b.z; acc[1][3] += a1*b.w;
        }
        __syncthreads();
    }
    #pragma unroll
    for (int i = 0; i < 2; i++) {
        int r = rowBase + ty*2 + i;
        float4 v = make_float4(acc[i][0], acc[i][1], acc[i][2], acc[i][3]);
        *reinterpret_cast<float4*>(C + (size_t)r * 64 + tx*4) = v;
    }
}

// ---------------- el/er projection: thread per (node, head) ---------------
__global__ __launch_bounds__(256) void attn_proj_kernel(const float* __restrict__ al,
                                                        const float* __restrict__ ar,
                                                        int H) {
    int idx = blockIdx.x * blockDim.x + threadIdx.x;
    if (idx >= N_NODES * H) return;
    int i = idx / H, h = idx - i * H;
    const float* xr = g_x + (size_t)i * D_H;
    float sl = 0.f, sr = 0.f;
    #pragma unroll
    for (int d = 0; d < D_H; d++) {
        float xv = xr[d];
        sl += xv * al[d * H + h];
        sr += xv * ar[d * H + h];
    }
    g_el[i * H + h] = sl;
    g_er[i * H + h] = sr;
}

// ---------------- attention aggregation: block per node -------------------
// blockDim = H*64 threads; thread = (h, d). Neighbors processed in CH chunks,
// feature rows staged in smem once per node (shared by all heads).
__global__ void agg_kernel(const float* __restrict__ bias,
                           float* __restrict__ out, int H, int act) {
    int i   = blockIdx.x;
    int tid = threadIdx.x;
    int h   = tid >> 6;
    int d   = tid & 63;

    __shared__ int   s_cols[CH];
    __shared__ float s_w[CH * HEADS];
    __shared__ float s_x[CH][D_H];

    int deg = g_deg[i];
    const int* cols = g_cols + (size_t)i * MAXD;
    float acc = 0.f, sw = 0.f;

    for (int j0 = 0; j0 < deg; j0 += CH) {
        int cl = min(CH, deg - j0);
        if (tid < cl) s_cols[tid] = cols[j0 + tid];
        __syncthreads();
        // attention weights for this chunk: cl * H values
        for (int idx = tid; idx < cl * H; idx += blockDim.x) {
            int jj = idx / H, hh = idx - jj * H;
            float s = g_el[i * H + hh] + g_er[s_cols[jj] * H + hh];
            s = (s >= 0.f) ? s : 0.2f * s;          // leaky_relu(0.2)
            s_w[jj * HEADS + hh] = expf(s);
        }
        // stage neighbor feature rows
        for (int idx = tid; idx < cl * D_H; idx += blockDim.x) {
            int jj = idx >> 6, dd = idx & 63;
            s_x[jj][dd] = g_x[(size_t)s_cols[jj] * D_H + dd];
        }
        __syncthreads();
        for (int jj = 0; jj < cl; jj++) {
            float wv = s_w[jj * HEADS + h];
            acc += wv * s_x[jj][d];
            sw  += wv;
        }
        __syncthreads();
    }

    float denom = fmaxf(sw, 1e-12f);
    float v = acc / denom + bias[d];
    if (act) v = (v > 0.f) ? v : expm1f(v);         // elu
    out[(size_t)i * (H * 64) + tid] = v;
}

// ---------------- launch ---------------------------------------------------
extern "C" void kernel_launch(void* const* d_in, const int* in_sizes, int n_in,
                              void* d_out, int out_size) {
    const float* adj  = (const float*)d_in[0];
    const float* feat = (const float*)d_in[1];
    const float* W0   = (const float*)d_in[2];
    const float* al0  = (const float*)d_in[3];
    const float* ar0  = (const float*)d_in[4];
    const float* b0   = (const float*)d_in[5];
    const float* W1   = (const float*)d_in[6];
    const float* al1  = (const float*)d_in[7];
    const float* ar1  = (const float*)d_in[8];
    const float* b1   = (const float*)d_in[9];
    const float* W2   = (const float*)d_in[10];
    const float* al2  = (const float*)d_in[11];
    const float* ar2  = (const float*)d_in[12];
    const float* b2   = (const float*)d_in[13];
    float* out = (float*)d_out;

    float *x, *h1, *h2;
    cudaGetSymbolAddress((void**)&x,  g_x);
    cudaGetSymbolAddress((void**)&h1, g_h1);
    cudaGetSymbolAddress((void**)&h2, g_h2);

    // CSR from adjacency (shared by all 3 layers)
    build_csr_kernel<<<N_NODES / 8, 256>>>(adj);

    const int gemm_grid = N_NODES / 32;   // 128 blocks
    const int proj_grid8 = (N_NODES * HEADS + 255) / 256;
    const int proj_grid1 = (N_NODES * 1 + 255) / 256;

    // layer 0: features -> h1  (8 heads, elu)
    gemm_kernel<<<gemm_grid, 256>>>(feat, W0, x);
    attn_proj_kernel<<<proj_grid8, 256>>>(al0, ar0, HEADS);
    agg_kernel<<<N_NODES, HEADS * 64>>>(b0, h1, HEADS, 1);

    // layer 1: h1 -> h2  (8 heads, elu)
    gemm_kernel<<<gemm_grid, 256>>>(h1, W1, x);
    attn_proj_kernel<<<proj_grid8, 256>>>(al1, ar1, HEADS);
    agg_kernel<<<N_NODES, HEADS * 64>>>(b1, h2, HEADS, 1);

    // layer 2: h2 -> out  (1 head, no activation)
    gemm_kernel<<<gemm_grid, 256>>>(h2, W2, x);
    attn_proj_kernel<<<proj_grid1, 256>>>(al2, ar2, 1);
    agg_kernel<<<N_NODES, 1 * 64>>>(b2, out, 1, 0);
}

// round 2
// speedup vs baseline: 1.3113x; 1.3113x over previous
#include <cuda_runtime.h>
#include <math.h>

#define N_NODES 4096
#define KDIM    512
#define D_H     64
#define HEADS   8
#define MAXD    192
#define CH      32

typedef unsigned long long ull;

// ---------------- packed f32x2 helpers (Blackwell) ----------------
__device__ __forceinline__ ull pack2(float a) {
    ull r;
    asm("mov.b64 %0, {%1, %1};" : "=l"(r) : "f"(a));
    return r;
}
__device__ __forceinline__ void fma2(ull& d, ull a, ull b) {
    asm("fma.rn.f32x2 %0, %1, %2, %0;" : "+l"(d) : "l"(a), "l"(b));
}
__device__ __forceinline__ void unpack2(ull v, float& lo, float& hi) {
    asm("mov.b64 {%0, %1}, %2;" : "=f"(lo), "=f"(hi) : "l"(v));
}

// ---------------- scratch ----------------
__device__ float g_x [N_NODES * D_H];
__device__ float g_el[N_NODES * HEADS];
__device__ float g_er[N_NODES * HEADS];
__device__ float g_h1[N_NODES * D_H * HEADS];
__device__ float g_h2[N_NODES * D_H * HEADS];
__device__ int   g_cols[N_NODES * MAXD];
__device__ int   g_deg [N_NODES];

// ---------------- CSR build: warp per row, ordered ballot compaction ------
__global__ __launch_bounds__(256) void build_csr_kernel(const float* __restrict__ adj) {
    int warp = (blockIdx.x * blockDim.x + threadIdx.x) >> 5;
    int lane = threadIdx.x & 31;
    if (warp >= N_NODES) return;
    const float4* a = reinterpret_cast<const float4*>(adj + (size_t)warp * N_NODES);
    int* out = g_cols + warp * MAXD;
    int base = 0;
    for (int j0 = 0; j0 < N_NODES; j0 += 128) {
        float4 v = a[(j0 >> 2) + lane];
        float vv[4] = {v.x, v.y, v.z, v.w};
        #pragma unroll
        for (int c = 0; c < 4; c++) {
            unsigned m = __ballot_sync(0xffffffffu, vv[c] != 0.0f);
            if (vv[c] != 0.0f) {
                int pos = base + __popc(m & ((1u << lane) - 1u));
                if (pos < MAXD) out[pos] = j0 + lane * 4 + c;
            }
            base += __popc(m);
        }
    }
    if (lane == 0) g_deg[warp] = base < MAXD ? base : MAXD;
}

// ---------------- GEMM: C[4096x64] = A[4096x512] @ B[512x64], packed f32x2 -
// BM=32, BN=64, BK=32, 256 threads, 2x4 micro-tile as 2x2 f32x2 pairs.
__global__ __launch_bounds__(256) void gemm_kernel(const float* __restrict__ A,
                                                   const float* __restrict__ B,
                                                   float* __restrict__ C) {
    __shared__ float As[32][33];
    __shared__ float Bs[32][64];
    int tid = threadIdx.x;
    int tx = tid & 15, ty = tid >> 4;
    int rowBase = blockIdx.x * 32;
    ull acc[2][2] = {{0ull, 0ull}, {0ull, 0ull}};

    for (int kt = 0; kt < KDIM; kt += 32) {
        {
            int r  = tid >> 3;
            int k4 = (tid & 7) << 2;
            float4 v = *reinterpret_cast<const float4*>(A + (size_t)(rowBase + r) * KDIM + kt + k4);
            As[r][k4+0] = v.x; As[r][k4+1] = v.y; As[r][k4+2] = v.z; As[r][k4+3] = v.w;
        }
        {
            int r  = tid >> 4;
            int c4 = (tid & 15) << 2;
            *reinterpret_cast<float4*>(&Bs[r][c4])      = *reinterpret_cast<const float4*>(B + (size_t)(kt + r)      * 64 + c4);
            *reinterpret_cast<float4*>(&Bs[r + 16][c4]) = *reinterpret_cast<const float4*>(B + (size_t)(kt + r + 16) * 64 + c4);
        }
        __syncthreads();
        #pragma unroll
        for (int k = 0; k < 32; k++) {
            ull pa0 = pack2(As[ty*2][k]);
            ull pa1 = pack2(As[ty*2+1][k]);
            ulonglong2 bb = *reinterpret_cast<const ulonglong2*>(&Bs[k][tx*4]);
            fma2(acc[0][0], pa0, bb.x);
            fma2(acc[0][1], pa0, bb.y);
            fma2(acc[1][0], pa1, bb.x);
            fma2(acc[1][1], pa1, bb.y);
        }
        __syncthreads();
    }
    #pragma unroll
    for (int i = 0; i < 2; i++) {
        int r = rowBase + ty*2 + i;
        ulonglong2 v;
        v.x = acc[i][0]; v.y = acc[i][1];
        *reinterpret_cast<ulonglong2*>(C + (size_t)r * 64 + tx*4) = v;
    }
}

// ---------------- el/er projection ---------------
__global__ __launch_bounds__(256) void attn_proj_kernel(const float* __restrict__ al,
                                                        const float* __restrict__ ar,
                                                        int H) {
    int idx = blockIdx.x * blockDim.x + threadIdx.x;
    if (idx >= N_NODES * H) return;
    int i = idx / H, h = idx - i * H;
    const float* xr = g_x + (size_t)i * D_H;
    float sl = 0.f, sr = 0.f;
    #pragma unroll
    for (int d = 0; d < D_H; d++) {
        float xv = xr[d];
        sl += xv * al[d * H + h];
        sr += xv * ar[d * H + h];
    }
    g_el[i * H + h] = sl;
    g_er[i * H + h] = sr;
}

// ---------------- 8-head aggregation: block per node, 128 threads ----------
// thread = (h, q): h in 0..7, q in 0..15; each thread owns 4 d values.
__global__ __launch_bounds__(128) void agg8_kernel(const float* __restrict__ bias,
                                                   float* __restrict__ out, int act) {
    int i   = blockIdx.x;
    int tid = threadIdx.x;
    int h   = tid >> 4;
    int q   = tid & 15;

    __shared__ int    s_cols[CH];
    __shared__ float  s_el[HEADS];
    __shared__ float  s_w[CH][HEADS];
    __shared__ float4 s_x[CH][16];

    if (tid < HEADS) s_el[tid] = g_el[i * HEADS + tid];
    int deg = g_deg[i];
    const int* cols = g_cols + (size_t)i * MAXD;

    ull acc0 = 0ull, acc1 = 0ull;
    float sw = 0.f;

    for (int j0 = 0; j0 < deg; j0 += CH) {
        int cl = min(CH, deg - j0);
        if (tid < cl) s_cols[tid] = cols[j0 + tid];
        __syncthreads();
        // weights: cl*8 values
        for (int idx = tid; idx < cl * HEADS; idx += 128) {
            int jj = idx >> 3, hh = idx & 7;
            float s = s_el[hh] + g_er[s_cols[jj] * HEADS + hh];
            s = (s >= 0.f) ? s : 0.2f * s;
            s_w[jj][hh] = __expf(s);
        }
        // stage neighbor rows (float4)
        for (int idx = tid; idx < cl * 16; idx += 128) {
            int jj = idx >> 4, qq = idx & 15;
            s_x[jj][qq] = *reinterpret_cast<const float4*>(g_x + (size_t)s_cols[jj] * D_H + qq * 4);
        }
        __syncthreads();
        for (int jj = 0; jj < cl; jj++) {
            float wv = s_w[jj][h];
            ull pw = pack2(wv);
            ulonglong2 xv = *reinterpret_cast<const ulonglong2*>(&s_x[jj][q]);
            fma2(acc0, pw, xv.x);
            fma2(acc1, pw, xv.y);
            sw += wv;
        }
        __syncthreads();
    }

    float inv = 1.0f / fmaxf(sw, 1e-12f);
    float4 bv = *reinterpret_cast<const float4*>(bias + q * 4);
    float v0, v1, v2, v3;
    unpack2(acc0, v0, v1);
    unpack2(acc1, v2, v3);
    v0 = v0 * inv + bv.x; v1 = v1 * inv + bv.y;
    v2 = v2 * inv + bv.z; v3 = v3 * inv + bv.w;
    if (act) {
        v0 = (v0 > 0.f) ? v0 : expm1f(v0);
        v1 = (v1 > 0.f) ? v1 : expm1f(v1);
        v2 = (v2 > 0.f) ? v2 : expm1f(v2);
        v3 = (v3 > 0.f) ? v3 : expm1f(v3);
    }
    float4 ov = make_float4(v0, v1, v2, v3);
    *reinterpret_cast<float4*>(out + (size_t)i * (HEADS * D_H) + h * D_H + q * 4) = ov;
}

// ---------------- 1-head aggregation: block per node, 64 threads -----------
__global__ __launch_bounds__(64) void agg1_kernel(const float* __restrict__ bias,
                                                  float* __restrict__ out) {
    int i   = blockIdx.x;
    int tid = threadIdx.x;   // = d

    __shared__ int   s_cols[CH];
    __shared__ float s_w[CH];
    __shared__ float s_x[CH][D_H];

    float eli = g_el[i];
    int deg = g_deg[i];
    const int* cols = g_cols + (size_t)i * MAXD;
    float acc = 0.f, sw = 0.f;

    for (int j0 = 0; j0 < deg; j0 += CH) {
        int cl = min(CH, deg - j0);
        if (tid < cl) {
            int c = cols[j0 + tid];
            s_cols[tid] = c;
            float s = eli + g_er[c];
            s = (s >= 0.f) ? s : 0.2f * s;
            s_w[tid] = __expf(s);
        }
        __syncthreads();
        for (int idx = tid; idx < cl * 16; idx += 64) {
            int jj = idx >> 4, qq = idx & 15;
            *reinterpret_cast<float4*>(&s_x[jj][qq * 4]) =
                *reinterpret_cast<const float4*>(g_x + (size_t)s_cols[jj] * D_H + qq * 4);
        }
        __syncthreads();
        for (int jj = 0; jj < cl; jj++) {
            float wv = s_w[jj];
            acc += wv * s_x[jj][tid];
            sw  += wv;
        }
        __syncthreads();
    }

    float v = acc / fmaxf(sw, 1e-12f) + bias[tid];
    out[(size_t)i * D_H + tid] = v;
}

// ---------------- launch ---------------------------------------------------
extern "C" void kernel_launch(void* const* d_in, const int* in_sizes, int n_in,
                              void* d_out, int out_size) {
    const float* adj  = (const float*)d_in[0];
    const float* feat = (const float*)d_in[1];
    const float* W0   = (const float*)d_in[2];
    const float* al0  = (const float*)d_in[3];
    const float* ar0  = (const float*)d_in[4];
    const float* b0   = (const float*)d_in[5];
    const float* W1   = (const float*)d_in[6];
    const float* al1  = (const float*)d_in[7];
    const float* ar1  = (const float*)d_in[8];
    const float* b1   = (const float*)d_in[9];
    const float* W2   = (const float*)d_in[10];
    const float* al2  = (const float*)d_in[11];
    const float* ar2  = (const float*)d_in[12];
    const float* b2   = (const float*)d_in[13];
    float* out = (float*)d_out;

    float *x, *h1, *h2;
    cudaGetSymbolAddress((void**)&x,  g_x);
    cudaGetSymbolAddress((void**)&h1, g_h1);
    cudaGetSymbolAddress((void**)&h2, g_h2);

    build_csr_kernel<<<N_NODES / 8, 256>>>(adj);

    const int gemm_grid = N_NODES / 32;
    const int proj_grid8 = (N_NODES * HEADS + 255) / 256;
    const int proj_grid1 = (N_NODES + 255) / 256;

    // layer 0
    gemm_kernel<<<gemm_grid, 256>>>(feat, W0, x);
    attn_proj_kernel<<<proj_grid8, 256>>>(al0, ar0, HEADS);
    agg8_kernel<<<N_NODES, 128>>>(b0, h1, 1);

    // layer 1
    gemm_kernel<<<gemm_grid, 256>>>(h1, W1, x);
    attn_proj_kernel<<<proj_grid8, 256>>>(al1, ar1, HEADS);
    agg8_kernel<<<N_NODES, 128>>>(b1, h2, 1);

    // layer 2
    gemm_kernel<<<gemm_grid, 256>>>(h2, W2, x);
    attn_proj_kernel<<<proj_grid1, 256>>>(al2, ar2, 1);
    agg1_kernel<<<N_NODES, 64>>>(b2, out);
}

// round 3
// speedup vs baseline: 1.6779x; 1.2796x over previous
#include <cuda_runtime.h>
#include <math.h>

#define N_NODES 4096
#define KDIM    512
#define D_H     64
#define HEADS   8
#define MAXD    192
#define CH      64

typedef unsigned long long ull;

// ---------------- packed f32x2 helpers (Blackwell) ----------------
__device__ __forceinline__ ull pack2(float a) {
    ull r;
    asm("mov.b64 %0, {%1, %1};" : "=l"(r) : "f"(a));
    return r;
}
__device__ __forceinline__ void fma2(ull& d, ull a, ull b) {
    asm("fma.rn.f32x2 %0, %1, %2, %0;" : "+l"(d) : "l"(a), "l"(b));
}
__device__ __forceinline__ void unpack2(ull v, float& lo, float& hi) {
    asm("mov.b64 {%0, %1}, %2;" : "=f"(lo), "=f"(hi) : "l"(v));
}

// ---------------- scratch ----------------
__device__ float g_x [N_NODES * D_H];
__device__ float g_el[N_NODES * HEADS];
__device__ float g_er[N_NODES * HEADS];
__device__ float g_h1[N_NODES * D_H * HEADS];
__device__ float g_h2[N_NODES * D_H * HEADS];
__device__ int   g_cols[N_NODES * MAXD];
__device__ int   g_deg [N_NODES];

// ---------------- CSR build: warp per row, ordered ballot compaction ------
__global__ __launch_bounds__(256) void build_csr_kernel(const float* __restrict__ adj) {
    int warp = (blockIdx.x * blockDim.x + threadIdx.x) >> 5;
    int lane = threadIdx.x & 31;
    if (warp >= N_NODES) return;
    const float4* a = reinterpret_cast<const float4*>(adj + (size_t)warp * N_NODES);
    int* out = g_cols + warp * MAXD;
    int base = 0;
    for (int j0 = 0; j0 < N_NODES; j0 += 128) {
        float4 v = a[(j0 >> 2) + lane];
        float vv[4] = {v.x, v.y, v.z, v.w};
        #pragma unroll
        for (int c = 0; c < 4; c++) {
            unsigned m = __ballot_sync(0xffffffffu, vv[c] != 0.0f);
            if (vv[c] != 0.0f) {
                int pos = base + __popc(m & ((1u << lane) - 1u));
                if (pos < MAXD) out[pos] = j0 + lane * 4 + c;
            }
            base += __popc(m);
        }
    }
    if (lane == 0) g_deg[warp] = base < MAXD ? base : MAXD;
}

// ---- GEMM + attn projection: C[4096x64] = A[4096x512] @ B[512x64] --------
// BM=32, BN=64, BK=32, 256 threads, register-prefetch double buffer.
// Epilogue: stage C tile in smem, compute el/er = C @ al / C @ ar.
__global__ __launch_bounds__(256) void gemm_proj_kernel(const float* __restrict__ A,
                                                        const float* __restrict__ B,
                                                        const float* __restrict__ al,
                                                        const float* __restrict__ ar,
                                                        float* __restrict__ C, int H) {
    __shared__ float As[32][33];
    __shared__ float Bs[32][64];
    int tid = threadIdx.x;
    int tx = tid & 15, ty = tid >> 4;
    int rowBase = blockIdx.x * 32;

    int arow = tid >> 3;            // 0..31
    int ak4  = (tid & 7) << 2;      // 0,4,..,28
    int brow = tid >> 4;            // 0..15
    int bc4  = (tid & 15) << 2;     // 0,4,..,60
    const float* Aptr  = A + (size_t)(rowBase + arow) * KDIM + ak4;
    const float* Bptr0 = B + (size_t)brow * 64 + bc4;
    const float* Bptr1 = B + (size_t)(brow + 16) * 64 + bc4;

    float4 a_n  = *reinterpret_cast<const float4*>(Aptr);
    float4 b0_n = *reinterpret_cast<const float4*>(Bptr0);
    float4 b1_n = *reinterpret_cast<const float4*>(Bptr1);

    ull acc[2][2] = {{0ull, 0ull}, {0ull, 0ull}};

    for (int kt = 0; kt < KDIM; kt += 32) {
        As[arow][ak4+0] = a_n.x; As[arow][ak4+1] = a_n.y;
        As[arow][ak4+2] = a_n.z; As[arow][ak4+3] = a_n.w;
        *reinterpret_cast<float4*>(&Bs[brow][bc4])      = b0_n;
        *reinterpret_cast<float4*>(&Bs[brow + 16][bc4]) = b1_n;
        __syncthreads();
        if (kt + 32 < KDIM) {   // prefetch next tile into registers
            a_n  = *reinterpret_cast<const float4*>(Aptr + kt + 32);
            b0_n = *reinterpret_cast<const float4*>(Bptr0 + (size_t)(kt + 32) * 64);
            b1_n = *reinterpret_cast<const float4*>(Bptr1 + (size_t)(kt + 32) * 64);
        }
        #pragma unroll
        for (int k = 0; k < 32; k++) {
            ull pa0 = pack2(As[ty*2][k]);
            ull pa1 = pack2(As[ty*2+1][k]);
            ulonglong2 bb = *reinterpret_cast<const ulonglong2*>(&Bs[k][tx*4]);
            fma2(acc[0][0], pa0, bb.x);
            fma2(acc[0][1], pa0, bb.y);
            fma2(acc[1][0], pa1, bb.x);
            fma2(acc[1][1], pa1, bb.y);
        }
        __syncthreads();
    }

    // write C to global + stage C tile into Bs for the projection epilogue
    #pragma unroll
    for (int i = 0; i < 2; i++) {
        int r = ty*2 + i;
        ulonglong2 v; v.x = acc[i][0]; v.y = acc[i][1];
        *reinterpret_cast<ulonglong2*>(C + (size_t)(rowBase + r) * 64 + tx*4) = v;
        *reinterpret_cast<ulonglong2*>(&Bs[r][tx*4]) = v;
    }
    // stage al/ar into As (flat): need 64*H*2 floats (<= 1024 <= 32*33)
    float* sA = &As[0][0];
    for (int idx = tid; idx < 64 * H; idx += 256) {
        sA[idx]          = al[idx];
        sA[64 * H + idx] = ar[idx];
    }
    __syncthreads();

    if (tid < 32 * H) {
        int r = (H == 8) ? (tid >> 3) : tid;
        int h = (H == 8) ? (tid & 7)  : 0;
        float sl = 0.f, sr = 0.f;
        #pragma unroll
        for (int d = 0; d < 64; d++) {
            float cv = Bs[r][d];
            sl += cv * sA[d * H + h];
            sr += cv * sA[64 * H + d * H + h];
        }
        g_el[(rowBase + r) * H + h] = sl;
        g_er[(rowBase + r) * H + h] = sr;
    }
}

// ---------------- 8-head aggregation: block per node, 128 threads ----------
__global__ __launch_bounds__(128) void agg8_kernel(const float* __restrict__ bias,
                                                   float* __restrict__ out, int act) {
    int i   = blockIdx.x;
    int tid = threadIdx.x;
    int h   = tid >> 4;
    int q   = tid & 15;

    __shared__ int    s_cols[CH];
    __shared__ float  s_el[HEADS];
    __shared__ float  s_w[CH][HEADS];
    __shared__ float4 s_x[CH][16];

    if (tid < HEADS) s_el[tid] = g_el[i * HEADS + tid];
    int deg = g_deg[i];
    const int* cols = g_cols + (size_t)i * MAXD;

    ull acc0 = 0ull, acc1 = 0ull;
    float sw = 0.f;

    for (int j0 = 0; j0 < deg; j0 += CH) {
        int cl = min(CH, deg - j0);
        if (tid < cl) s_cols[tid] = cols[j0 + tid];
        __syncthreads();
        for (int idx = tid; idx < cl * HEADS; idx += 128) {
            int jj = idx >> 3, hh = idx & 7;
            float s = s_el[hh] + g_er[s_cols[jj] * HEADS + hh];
            s = (s >= 0.f) ? s : 0.2f * s;
            s_w[jj][hh] = __expf(s);
        }
        for (int idx = tid; idx < cl * 16; idx += 128) {
            int jj = idx >> 4, qq = idx & 15;
            s_x[jj][qq] = *reinterpret_cast<const float4*>(g_x + (size_t)s_cols[jj] * D_H + qq * 4);
        }
        __syncthreads();
        for (int jj = 0; jj < cl; jj++) {
            float wv = s_w[jj][h];
            ull pw = pack2(wv);
            ulonglong2 xv = *reinterpret_cast<const ulonglong2*>(&s_x[jj][q]);
            fma2(acc0, pw, xv.x);
            fma2(acc1, pw, xv.y);
            sw += wv;
        }
        __syncthreads();
    }

    float inv = 1.0f / fmaxf(sw, 1e-12f);
    float4 bv = *reinterpret_cast<const float4*>(bias + q * 4);
    float v0, v1, v2, v3;
    unpack2(acc0, v0, v1);
    unpack2(acc1, v2, v3);
    v0 = v0 * inv + bv.x; v1 = v1 * inv + bv.y;
    v2 = v2 * inv + bv.z; v3 = v3 * inv + bv.w;
    if (act) {
        v0 = (v0 > 0.f) ? v0 : expm1f(v0);
        v1 = (v1 > 0.f) ? v1 : expm1f(v1);
        v2 = (v2 > 0.f) ? v2 : expm1f(v2);
        v3 = (v3 > 0.f) ? v3 : expm1f(v3);
    }
    float4 ov = make_float4(v0, v1, v2, v3);
    *reinterpret_cast<float4*>(out + (size_t)i * (HEADS * D_H) + h * D_H + q * 4) = ov;
}

// ---------------- 1-head aggregation: block per node, 64 threads -----------
__global__ __launch_bounds__(64) void agg1_kernel(const float* __restrict__ bias,
                                                  float* __restrict__ out) {
    int i   = blockIdx.x;
    int tid = threadIdx.x;   // = d

    __shared__ int   s_cols[CH];
    __shared__ float s_w[CH];
    __shared__ float s_x[CH][D_H];

    float eli = g_el[i];
    int deg = g_deg[i];
    const int* cols = g_cols + (size_t)i * MAXD;
    float acc = 0.f, sw = 0.f;

    for (int j0 = 0; j0 < deg; j0 += CH) {
        int cl = min(CH, deg - j0);
        if (tid < cl) {
            int c = cols[j0 + tid];
            s_cols[tid] = c;
            float s = eli + g_er[c];
            s = (s >= 0.f) ? s : 0.2f * s;
            s_w[tid] = __expf(s);
        }
        __syncthreads();
        for (int idx = tid; idx < cl * 16; idx += 64) {
            int jj = idx >> 4, qq = idx & 15;
            *reinterpret_cast<float4*>(&s_x[jj][qq * 4]) =
                *reinterpret_cast<const float4*>(g_x + (size_t)s_cols[jj] * D_H + qq * 4);
        }
        __syncthreads();
        for (int jj = 0; jj < cl; jj++) {
            float wv = s_w[jj];
            acc += wv * s_x[jj][tid];
            sw  += wv;
        }
        __syncthreads();
    }

    float v = acc / fmaxf(sw, 1e-12f) + bias[tid];
    out[(size_t)i * D_H + tid] = v;
}

// ---------------- launch ---------------------------------------------------
extern "C" void kernel_launch(void* const* d_in, const int* in_sizes, int n_in,
                              void* d_out, int out_size) {
    const float* adj  = (const float*)d_in[0];
    const float* feat = (const float*)d_in[1];
    const float* W0   = (const float*)d_in[2];
    const float* al0  = (const float*)d_in[3];
    const float* ar0  = (const float*)d_in[4];
    const float* b0   = (const float*)d_in[5];
    const float* W1   = (const float*)d_in[6];
    const float* al1  = (const float*)d_in[7];
    const float* ar1  = (const float*)d_in[8];
    const float* b1   = (const float*)d_in[9];
    const float* W2   = (const float*)d_in[10];
    const float* al2  = (const float*)d_in[11];
    const float* ar2  = (const float*)d_in[12];
    const float* b2   = (const float*)d_in[13];
    float* out = (float*)d_out;

    float *x, *h1, *h2;
    cudaGetSymbolAddress((void**)&x,  g_x);
    cudaGetSymbolAddress((void**)&h1, g_h1);
    cudaGetSymbolAddress((void**)&h2, g_h2);

    build_csr_kernel<<<N_NODES / 8, 256>>>(adj);

    const int gemm_grid = N_NODES / 32;   // 128 blocks

    // layer 0
    gemm_proj_kernel<<<gemm_grid, 256>>>(feat, W0, al0, ar0, x, HEADS);
    agg8_kernel<<<N_NODES, 128>>>(b0, h1, 1);

    // layer 1
    gemm_proj_kernel<<<gemm_grid, 256>>>(h1, W1, al1, ar1, x, HEADS);
    agg8_kernel<<<N_NODES, 128>>>(b1, h2, 1);

    // layer 2
    gemm_proj_kernel<<<gemm_grid, 256>>>(h2, W2, al2, ar2, x, 1);
    agg1_kernel<<<N_NODES, 64>>>(b2, out);
}